// round 2
// baseline (speedup 1.0000x reference)
#include <cuda_runtime.h>
#include <cstdint>

#define N_NODES 100000
#define NFEAT   256
#define NHID    128
#define NHID2   64

// Scratch (no cudaMalloc allowed)
__device__ float g_H0[(size_t)N_NODES * NHID];   // x @ W1
__device__ float g_S1[(size_t)N_NODES * NHID];   // spmm(adj, H0)
__device__ float g_H2[(size_t)N_NODES * NHID2];  // relu(S1+b1) @ W2

// ---------------------------------------------------------------------------
// Zero-fill (float4 grid-stride)
// ---------------------------------------------------------------------------
__global__ void zero_kernel(float4* p, size_t n4) {
    size_t i = (size_t)blockIdx.x * blockDim.x + threadIdx.x;
    size_t stride = (size_t)gridDim.x * blockDim.x;
    float4 z = make_float4(0.f, 0.f, 0.f, 0.f);
    for (; i < n4; i += stride) p[i] = z;
}

// ---------------------------------------------------------------------------
// Tiled SGEMM: C[M,N] = op(A)[M,K] @ B[K,N]
// If INREL: A element (m,k) -> relu(A[m,k] + bias_in[k])  (fuses the
// bias+ReLU between spmm1 output and GEMM2 input).
// ---------------------------------------------------------------------------
template <int BM, int BN, int BK, int TM, int TN, bool INREL>
__global__ void sgemm_kernel(const float* __restrict__ A,
                             const float* __restrict__ B,
                             const float* __restrict__ bias_in,
                             float* __restrict__ C,
                             int M, int N, int K) {
    constexpr int THREADS = (BM / TM) * (BN / TN);
    __shared__ float As[BK][BM + 4];   // transposed A tile (k-major)
    __shared__ float Bs[BK][BN];

    const int tid = threadIdx.x;
    const int tx = tid % (BN / TN);
    const int ty = tid / (BN / TN);
    const int mBase = blockIdx.x * BM;

    float acc[TM][TN];
#pragma unroll
    for (int i = 0; i < TM; i++)
#pragma unroll
        for (int j = 0; j < TN; j++) acc[i][j] = 0.f;

    constexpr int A_LOADS = (BM * BK / 4) / THREADS;
    constexpr int B_LOADS = (BK * BN / 4) / THREADS;

    for (int k0 = 0; k0 < K; k0 += BK) {
        // --- load A tile (transpose to k-major in smem) ---
#pragma unroll
        for (int i = 0; i < A_LOADS; i++) {
            int idx = tid + i * THREADS;
            int row = idx / (BK / 4);
            int k4  = (idx % (BK / 4)) * 4;
            float4 v = make_float4(0.f, 0.f, 0.f, 0.f);
            int grow = mBase + row;
            if (grow < M)
                v = *reinterpret_cast<const float4*>(&A[(size_t)grow * K + k0 + k4]);
            if (INREL) {
                float4 bv = *reinterpret_cast<const float4*>(&bias_in[k0 + k4]);
                v.x = fmaxf(v.x + bv.x, 0.f);
                v.y = fmaxf(v.y + bv.y, 0.f);
                v.z = fmaxf(v.z + bv.z, 0.f);
                v.w = fmaxf(v.w + bv.w, 0.f);
            }
            As[k4 + 0][row] = v.x;
            As[k4 + 1][row] = v.y;
            As[k4 + 2][row] = v.z;
            As[k4 + 3][row] = v.w;
        }
        // --- load B tile ---
#pragma unroll
        for (int i = 0; i < B_LOADS; i++) {
            int idx = tid + i * THREADS;
            int krow = idx / (BN / 4);
            int c4   = (idx % (BN / 4)) * 4;
            *reinterpret_cast<float4*>(&Bs[krow][c4]) =
                *reinterpret_cast<const float4*>(&B[(size_t)(k0 + krow) * N + c4]);
        }
        __syncthreads();

#pragma unroll
        for (int k = 0; k < BK; k++) {
            float a[TM], b[TN];
#pragma unroll
            for (int i = 0; i < TM; i++) a[i] = As[k][ty * TM + i];
#pragma unroll
            for (int j = 0; j < TN; j++) b[j] = Bs[k][tx * TN + j];
#pragma unroll
            for (int i = 0; i < TM; i++)
#pragma unroll
                for (int j = 0; j < TN; j++) acc[i][j] = fmaf(a[i], b[j], acc[i][j]);
        }
        __syncthreads();
    }

    // --- store ---
#pragma unroll
    for (int i = 0; i < TM; i++) {
        int grow = mBase + ty * TM + i;
        if (grow < M) {
#pragma unroll
            for (int j4 = 0; j4 < TN; j4 += 4) {
                float4 v = make_float4(acc[i][j4], acc[i][j4 + 1],
                                       acc[i][j4 + 2], acc[i][j4 + 3]);
                *reinterpret_cast<float4*>(&C[(size_t)grow * N + tx * TN + j4]) = v;
            }
        }
    }
}

// ---------------------------------------------------------------------------
// SpMM for sorted-COO: S[r] += v * H[c] per edge. One block handles EPB
// consecutive edges; thread t owns feature column t. Sorted rows -> register
// run-length accumulation, atomicAdd only at row changes / chunk boundaries.
// NOTE: edge indices are int32 (JAX x64 disabled: astype(int64) -> int32).
// ---------------------------------------------------------------------------
template <int F>
__global__ void spmm_kernel(const float* __restrict__ vals,
                            const int* __restrict__ rows,
                            const int* __restrict__ cols,
                            const float* __restrict__ H,
                            float* __restrict__ S,
                            int E, int EPB) {
    const int tid = threadIdx.x;
    int e0 = blockIdx.x * EPB;
    int e1 = e0 + EPB;
    if (e1 > E) e1 = E;
    if (e0 >= e1) return;

    int cur = rows[e0];
    float acc = 0.f;
    for (int e = e0; e < e1; e++) {
        int r = rows[e];
        int c = cols[e];
        float v = __ldg(&vals[e]);
        float h = __ldg(&H[(size_t)c * F + tid]);
        if (r != cur) {
            atomicAdd(&S[(size_t)cur * F + tid], acc);
            acc = 0.f;
            cur = r;
        }
        acc = fmaf(v, h, acc);
    }
    atomicAdd(&S[(size_t)cur * F + tid], acc);
}

// ---------------------------------------------------------------------------
// In-place bias + ReLU on the final output
// ---------------------------------------------------------------------------
__global__ void bias_relu_kernel(float* __restrict__ out,
                                 const float* __restrict__ bias,
                                 size_t n, int F) {
    size_t i = (size_t)blockIdx.x * blockDim.x + threadIdx.x;
    size_t stride = (size_t)gridDim.x * blockDim.x;
    for (; i < n; i += stride) {
        int col = (int)(i % F);
        out[i] = fmaxf(out[i] + bias[col], 0.f);
    }
}

// ---------------------------------------------------------------------------
extern "C" void kernel_launch(void* const* d_in, const int* in_sizes, int n_in,
                              void* d_out, int out_size) {
    const float* x     = (const float*)d_in[0];
    const float* W1    = (const float*)d_in[1];
    const float* b1    = (const float*)d_in[2];
    const float* W2    = (const float*)d_in[3];
    const float* b2    = (const float*)d_in[4];
    const float* evals = (const float*)d_in[5];
    const int*   erows = (const int*)d_in[6];
    const int*   ecols = (const int*)d_in[7];
    float*       out   = (float*)d_out;

    const int E = in_sizes[5];

    void *pH0, *pS1, *pH2;
    cudaGetSymbolAddress(&pH0, g_H0);
    cudaGetSymbolAddress(&pS1, g_S1);
    cudaGetSymbolAddress(&pH2, g_H2);
    float* H0 = (float*)pH0;
    float* S1 = (float*)pS1;
    float* H2 = (float*)pH2;

    // zero accumulators
    {
        size_t n4 = (size_t)N_NODES * NHID / 4;
        zero_kernel<<<1024, 256>>>((float4*)S1, n4);
        size_t n4o = (size_t)N_NODES * NHID2 / 4;
        zero_kernel<<<1024, 256>>>((float4*)out, n4o);
    }

    // GEMM1: H0 = x @ W1   (M=100000, N=128, K=256)
    {
        constexpr int BM = 64, BN = 128, BK = 32, TM = 4, TN = 8;
        int grid = (N_NODES + BM - 1) / BM;
        sgemm_kernel<BM, BN, BK, TM, TN, false><<<grid, 256>>>(
            x, W1, nullptr, H0, N_NODES, NHID, NFEAT);
    }

    // SpMM1: S1 = A @ H0
    {
        const int EPB = 256;
        int grid = (E + EPB - 1) / EPB;
        spmm_kernel<NHID><<<grid, NHID>>>(evals, erows, ecols, H0, S1, E, EPB);
    }

    // GEMM2: H2 = relu(S1 + b1) @ W2   (M=100000, N=64, K=128)
    {
        constexpr int BM = 64, BN = 64, BK = 32, TM = 4, TN = 4;
        int grid = (N_NODES + BM - 1) / BM;
        sgemm_kernel<BM, BN, BK, TM, TN, true><<<grid, 256>>>(
            S1, W2, b1, H2, N_NODES, NHID2, NHID);
    }

    // SpMM2: out += A @ H2
    {
        const int EPB = 256;
        int grid = (E + EPB - 1) / EPB;
        spmm_kernel<NHID2><<<grid, NHID2>>>(evals, erows, ecols, H2, out, E, EPB);
    }

    // out = relu(out + b2)
    {
        size_t n = (size_t)N_NODES * NHID2;
        bias_relu_kernel<<<2048, 256>>>(out, b2, n, NHID2);
    }
}

// round 3
// speedup vs baseline: 1.9560x; 1.9560x over previous
#include <cuda_runtime.h>
#include <cstdint>

#define N_NODES 100000
#define NFEAT   256
#define NHID    128
#define NHID2   64

// Scratch (no cudaMalloc allowed)
__device__ float g_H0[(size_t)N_NODES * NHID];    // x @ W1
__device__ float g_H1[(size_t)N_NODES * NHID];    // relu(spmm(A,H0)+b1)
__device__ float g_H2[(size_t)N_NODES * NHID2];   // H1 @ W2
__device__ int   g_rowptr[N_NODES + 1];

// ---------------------------------------------------------------------------
// row_ptr from sorted COO rows: rp[i] = lower_bound(rows, i)
// ---------------------------------------------------------------------------
__global__ void rowptr_kernel(const int* __restrict__ rows, int E,
                              int* __restrict__ rp) {
    int i = blockIdx.x * blockDim.x + threadIdx.x;
    if (i > N_NODES) return;
    int lo = 0, hi = E;
    while (lo < hi) {
        int mid = (lo + hi) >> 1;
        if (rows[mid] < i) lo = mid + 1; else hi = mid;
    }
    rp[i] = lo;
}

// ---------------------------------------------------------------------------
// TF32 helpers (3xTF32 split for ~fp32 accuracy on tensor cores)
// ---------------------------------------------------------------------------
__device__ __forceinline__ void split_tf32(float x, uint32_t& hi, uint32_t& lo) {
    asm("cvt.rna.tf32.f32 %0, %1;" : "=r"(hi) : "f"(x));
    float hif = __uint_as_float(hi);
    float lof = x - hif;
    asm("cvt.rna.tf32.f32 %0, %1;" : "=r"(lo) : "f"(lof));
}

__device__ __forceinline__ void mma_tf32(float* d, const uint32_t* a,
                                         const uint32_t* b) {
    asm("mma.sync.aligned.m16n8k8.row.col.f32.tf32.tf32.f32 "
        "{%0,%1,%2,%3},{%4,%5,%6,%7},{%8,%9},{%0,%1,%2,%3};"
        : "+f"(d[0]), "+f"(d[1]), "+f"(d[2]), "+f"(d[3])
        : "r"(a[0]), "r"(a[1]), "r"(a[2]), "r"(a[3]), "r"(b[0]), "r"(b[1]));
}

// ---------------------------------------------------------------------------
// Tensor-core GEMM: C[M,N] = A[M,K] @ B[K,N], fp32 in/out, 3xTF32 internally.
// Block 256 thr, tile BM=128 x BN=64, BK=32. Warps: 4(m) x 2(n), warp=32x32.
// ---------------------------------------------------------------------------
#define GBM 128
#define GBN 64
#define GBK 32

__global__ __launch_bounds__(256) void gemm_tf32_kernel(
    const float* __restrict__ A, const float* __restrict__ B,
    float* __restrict__ C, int M, int N, int K) {
    __shared__ float As[GBM][GBK + 4];
    __shared__ float Bs[GBK][GBN + 4];

    const int tid  = threadIdx.x;
    const int wid  = tid >> 5, lane = tid & 31;
    const int g    = lane >> 2, tig = lane & 3;
    const int warp_m = wid >> 1, warp_n = wid & 1;
    const int mBase = blockIdx.x * GBM;
    const int nBase = blockIdx.y * GBN;
    const int KT = K / GBK;

    float acc[2][4][4];
#pragma unroll
    for (int mi = 0; mi < 2; mi++)
#pragma unroll
        for (int ni = 0; ni < 4; ni++)
#pragma unroll
            for (int r = 0; r < 4; r++) acc[mi][ni][r] = 0.f;

    float4 aReg[4], bReg[2];

    auto loadTile = [&](int kt) {
#pragma unroll
        for (int i = 0; i < 4; i++) {
            int idx = tid + i * 256;
            int row = idx >> 3, kc = (idx & 7) << 2;
            int grow = mBase + row;
            float4 v = make_float4(0.f, 0.f, 0.f, 0.f);
            if (grow < M)
                v = *reinterpret_cast<const float4*>(
                        &A[(size_t)grow * K + kt * GBK + kc]);
            aReg[i] = v;
        }
#pragma unroll
        for (int i = 0; i < 2; i++) {
            int idx = tid + i * 256;
            int kr = idx >> 4, nc = (idx & 15) << 2;
            bReg[i] = *reinterpret_cast<const float4*>(
                          &B[(size_t)(kt * GBK + kr) * N + nBase + nc]);
        }
    };
    auto stageTile = [&]() {
#pragma unroll
        for (int i = 0; i < 4; i++) {
            int idx = tid + i * 256;
            int row = idx >> 3, kc = (idx & 7) << 2;
            *reinterpret_cast<float4*>(&As[row][kc]) = aReg[i];
        }
#pragma unroll
        for (int i = 0; i < 2; i++) {
            int idx = tid + i * 256;
            int kr = idx >> 4, nc = (idx & 15) << 2;
            *reinterpret_cast<float4*>(&Bs[kr][nc]) = bReg[i];
        }
    };

    loadTile(0);
    stageTile();
    __syncthreads();

    for (int kt = 0; kt < KT; kt++) {
        if (kt + 1 < KT) loadTile(kt + 1);

#pragma unroll
        for (int ka = 0; ka < 4; ka++) {
            uint32_t ah[2][4], al[2][4], bh[4][2], bl[4][2];
#pragma unroll
            for (int mi = 0; mi < 2; mi++) {
                int row = warp_m * 32 + mi * 16 + g;
                int k0 = ka * 8 + tig;
                split_tf32(As[row][k0],       ah[mi][0], al[mi][0]);
                split_tf32(As[row + 8][k0],   ah[mi][1], al[mi][1]);
                split_tf32(As[row][k0 + 4],   ah[mi][2], al[mi][2]);
                split_tf32(As[row + 8][k0+4], ah[mi][3], al[mi][3]);
            }
#pragma unroll
            for (int ni = 0; ni < 4; ni++) {
                int col = warp_n * 32 + ni * 8 + g;
                split_tf32(Bs[ka * 8 + tig][col],     bh[ni][0], bl[ni][0]);
                split_tf32(Bs[ka * 8 + tig + 4][col], bh[ni][1], bl[ni][1]);
            }
#pragma unroll
            for (int mi = 0; mi < 2; mi++)
#pragma unroll
                for (int ni = 0; ni < 4; ni++) {
                    mma_tf32(acc[mi][ni], ah[mi], bh[ni]);
                    mma_tf32(acc[mi][ni], ah[mi], bl[ni]);
                    mma_tf32(acc[mi][ni], al[mi], bh[ni]);
                }
        }
        __syncthreads();
        if (kt + 1 < KT) {
            stageTile();
            __syncthreads();
        }
    }

    // store
#pragma unroll
    for (int mi = 0; mi < 2; mi++) {
        int row = mBase + warp_m * 32 + mi * 16 + g;
#pragma unroll
        for (int ni = 0; ni < 4; ni++) {
            int col = nBase + warp_n * 32 + ni * 8 + 2 * tig;
            if (row < M)
                *reinterpret_cast<float2*>(&C[(size_t)row * N + col]) =
                    make_float2(acc[mi][ni][0], acc[mi][ni][1]);
            if (row + 8 < M)
                *reinterpret_cast<float2*>(&C[(size_t)(row + 8) * N + col]) =
                    make_float2(acc[mi][ni][2], acc[mi][ni][3]);
        }
    }
}

// ---------------------------------------------------------------------------
// CSR SpMM, warp per node, no atomics. F=128: float4/lane. Fused bias+ReLU.
// ---------------------------------------------------------------------------
__global__ __launch_bounds__(256) void spmm_csr_f128(
    const float* __restrict__ vals, const int* __restrict__ cols,
    const int* __restrict__ rp, const float4* __restrict__ H4,
    const float4* __restrict__ bias4, float4* __restrict__ out4) {
    int node = blockIdx.x * (blockDim.x >> 5) + (threadIdx.x >> 5);
    int lane = threadIdx.x & 31;
    if (node >= N_NODES) return;
    int s = rp[node], e = rp[node + 1];

    float4 acc = make_float4(0.f, 0.f, 0.f, 0.f);
    int i = s;
    for (; i + 4 <= e; i += 4) {
        int c0 = cols[i], c1 = cols[i + 1], c2 = cols[i + 2], c3 = cols[i + 3];
        float v0 = vals[i], v1 = vals[i + 1], v2 = vals[i + 2], v3 = vals[i + 3];
        float4 h0 = H4[(size_t)c0 * 32 + lane];
        float4 h1 = H4[(size_t)c1 * 32 + lane];
        float4 h2 = H4[(size_t)c2 * 32 + lane];
        float4 h3 = H4[(size_t)c3 * 32 + lane];
        acc.x = fmaf(v0, h0.x, acc.x); acc.y = fmaf(v0, h0.y, acc.y);
        acc.z = fmaf(v0, h0.z, acc.z); acc.w = fmaf(v0, h0.w, acc.w);
        acc.x = fmaf(v1, h1.x, acc.x); acc.y = fmaf(v1, h1.y, acc.y);
        acc.z = fmaf(v1, h1.z, acc.z); acc.w = fmaf(v1, h1.w, acc.w);
        acc.x = fmaf(v2, h2.x, acc.x); acc.y = fmaf(v2, h2.y, acc.y);
        acc.z = fmaf(v2, h2.z, acc.z); acc.w = fmaf(v2, h2.w, acc.w);
        acc.x = fmaf(v3, h3.x, acc.x); acc.y = fmaf(v3, h3.y, acc.y);
        acc.z = fmaf(v3, h3.z, acc.z); acc.w = fmaf(v3, h3.w, acc.w);
    }
    for (; i < e; i++) {
        int c = cols[i];
        float v = vals[i];
        float4 h = H4[(size_t)c * 32 + lane];
        acc.x = fmaf(v, h.x, acc.x); acc.y = fmaf(v, h.y, acc.y);
        acc.z = fmaf(v, h.z, acc.z); acc.w = fmaf(v, h.w, acc.w);
    }
    float4 b = bias4[lane];
    acc.x = fmaxf(acc.x + b.x, 0.f);
    acc.y = fmaxf(acc.y + b.y, 0.f);
    acc.z = fmaxf(acc.z + b.z, 0.f);
    acc.w = fmaxf(acc.w + b.w, 0.f);
    out4[(size_t)node * 32 + lane] = acc;
}

// F=64: float2 per lane
__global__ __launch_bounds__(256) void spmm_csr_f64(
    const float* __restrict__ vals, const int* __restrict__ cols,
    const int* __restrict__ rp, const float2* __restrict__ H2,
    const float2* __restrict__ bias2, float2* __restrict__ out2) {
    int node = blockIdx.x * (blockDim.x >> 5) + (threadIdx.x >> 5);
    int lane = threadIdx.x & 31;
    if (node >= N_NODES) return;
    int s = rp[node], e = rp[node + 1];

    float2 acc = make_float2(0.f, 0.f);
    int i = s;
    for (; i + 4 <= e; i += 4) {
        int c0 = cols[i], c1 = cols[i + 1], c2 = cols[i + 2], c3 = cols[i + 3];
        float v0 = vals[i], v1 = vals[i + 1], v2 = vals[i + 2], v3 = vals[i + 3];
        float2 h0 = H2[(size_t)c0 * 32 + lane];
        float2 h1 = H2[(size_t)c1 * 32 + lane];
        float2 h2 = H2[(size_t)c2 * 32 + lane];
        float2 h3 = H2[(size_t)c3 * 32 + lane];
        acc.x = fmaf(v0, h0.x, acc.x); acc.y = fmaf(v0, h0.y, acc.y);
        acc.x = fmaf(v1, h1.x, acc.x); acc.y = fmaf(v1, h1.y, acc.y);
        acc.x = fmaf(v2, h2.x, acc.x); acc.y = fmaf(v2, h2.y, acc.y);
        acc.x = fmaf(v3, h3.x, acc.x); acc.y = fmaf(v3, h3.y, acc.y);
    }
    for (; i < e; i++) {
        int c = cols[i];
        float v = vals[i];
        float2 h = H2[(size_t)c * 32 + lane];
        acc.x = fmaf(v, h.x, acc.x); acc.y = fmaf(v, h.y, acc.y);
    }
    float2 b = bias2[lane];
    acc.x = fmaxf(acc.x + b.x, 0.f);
    acc.y = fmaxf(acc.y + b.y, 0.f);
    out2[(size_t)node * 32 + lane] = acc;
}

// ---------------------------------------------------------------------------
extern "C" void kernel_launch(void* const* d_in, const int* in_sizes, int n_in,
                              void* d_out, int out_size) {
    const float* x     = (const float*)d_in[0];
    const float* W1    = (const float*)d_in[1];
    const float* b1    = (const float*)d_in[2];
    const float* W2    = (const float*)d_in[3];
    const float* b2    = (const float*)d_in[4];
    const float* evals = (const float*)d_in[5];
    const int*   erows = (const int*)d_in[6];
    const int*   ecols = (const int*)d_in[7];
    float*       out   = (float*)d_out;

    const int E = in_sizes[5];

    void *pH0, *pH1, *pH2, *pRP;
    cudaGetSymbolAddress(&pH0, g_H0);
    cudaGetSymbolAddress(&pH1, g_H1);
    cudaGetSymbolAddress(&pH2, g_H2);
    cudaGetSymbolAddress(&pRP, g_rowptr);
    float* H0 = (float*)pH0;
    float* H1 = (float*)pH1;
    float* H2 = (float*)pH2;
    int*   rp = (int*)pRP;

    // row_ptr from sorted rows
    rowptr_kernel<<<(N_NODES + 1 + 255) / 256, 256>>>(erows, E, rp);

    // GEMM1: H0 = x @ W1   (M=100000, N=128, K=256)
    {
        dim3 grid((N_NODES + GBM - 1) / GBM, NHID / GBN);
        gemm_tf32_kernel<<<grid, 256>>>(x, W1, H0, N_NODES, NHID, NFEAT);
    }

    // SpMM1: H1 = relu(A @ H0 + b1)
    {
        int warps_per_block = 8;
        int grid = (N_NODES + warps_per_block - 1) / warps_per_block;
        spmm_csr_f128<<<grid, 256>>>(evals, ecols, rp, (const float4*)H0,
                                     (const float4*)b1, (float4*)H1);
    }

    // GEMM2: H2 = H1 @ W2   (M=100000, N=64, K=128)
    {
        dim3 grid((N_NODES + GBM - 1) / GBM, NHID2 / GBN);
        gemm_tf32_kernel<<<grid, 256>>>(H1, W2, H2, N_NODES, NHID2, NHID);
    }

    // SpMM2: out = relu(A @ H2 + b2)
    {
        int warps_per_block = 8;
        int grid = (N_NODES + warps_per_block - 1) / warps_per_block;
        spmm_csr_f64<<<grid, 256>>>(evals, ecols, rp, (const float2*)H2,
                                    (const float2*)b2, (float2*)out);
    }
}